// round 15
// baseline (speedup 1.0000x reference)
#include <cuda_runtime.h>
#include <cstdint>

// Dims: B=8, C=1024, T=512, HW=49, D=128, window=101, out_dim=128.

__device__ float g_xm  [8u * 1024u * 512u];  // [B, C, T] spatial means (16.8 MB)
__device__ float g_part[8u * 4096u * 128u];  // [ksplit][b*T+t][d] GEMM partials
__device__ float g_y   [4096u * 128u];       // [B*T, 128] normalized projections

#define CP_ASYNC16(dst_u32, src_ptr) \
    asm volatile("cp.async.cg.shared.global [%0], [%1], 16;\n" \
                 :: "r"(dst_u32), "l"(src_ptr))
#define CP_COMMIT() asm volatile("cp.async.commit_group;\n" ::: "memory")
#define CP_WAIT1()  asm volatile("cp.async.wait_group 1;\n" ::: "memory")
#define CP_WAIT0()  asm volatile("cp.async.wait_group 0;\n" ::: "memory")

// Packed fp32x2 FMA (sm_100+): d = a*b + d per 32-bit half. FFMA2 in SASS.
__device__ __forceinline__ void fma2(unsigned long long& d,
                                     unsigned long long a,
                                     unsigned long long b) {
    asm("fma.rn.f32x2 %0, %1, %2, %0;" : "+l"(d) : "l"(a), "l"(b));
}
__device__ __forceinline__ unsigned long long bcast2(float x) {
    unsigned long long r;
    unsigned int u = __float_as_uint(x);
    asm("mov.b64 %0, {%1, %1};" : "=l"(r) : "r"(u));
    return r;
}
__device__ __forceinline__ float lo32(unsigned long long v) {
    return __uint_as_float((unsigned int)(v & 0xffffffffull));
}
__device__ __forceinline__ float hi32(unsigned long long v) {
    return __uint_as_float((unsigned int)(v >> 32));
}

// ---------------------------------------------------------------------------
// Kernel 1 (proven, R13): spatial mean over 49 — persistent block, 4 tiles,
// 2-stage static double-buffered cp.async. Tile = 128 rows = 25088 floats.
// Stride-49 smem reads conflict-free (gcd(49,32)=1).
// ---------------------------------------------------------------------------
__global__ void __launch_bounds__(256) k_mean(const float* __restrict__ in) {
    __shared__ __align__(16) float s[2][128 * 49];   // 2 x 25088 B
    int tid = threadIdx.x;
    unsigned int sb[2];
    sb[0] = (unsigned int)__cvta_generic_to_shared(s[0]);
    sb[1] = (unsigned int)__cvta_generic_to_shared(s[1]);
    size_t t0 = (size_t)blockIdx.x * 4;

    auto issue = [&](unsigned int base, size_t tile) {
        const float4* src = (const float4*)in + tile * 1568;
        #pragma unroll
        for (int i = 0; i < 6; i++) {
            int j = tid + i * 256;
            CP_ASYNC16(base + j * 16, src + j);
        }
        int j = tid + 1536;
        if (j < 1568) CP_ASYNC16(base + j * 16, src + j);
        CP_COMMIT();
    };

    issue(sb[0], t0);
    issue(sb[1], t0 + 1);

    #pragma unroll
    for (int i = 0; i < 4; i++) {
        if (i < 3) { CP_WAIT1(); } else { CP_WAIT0(); }
        __syncthreads();
        if (tid < 128) {
            const float* p = s[i & 1] + tid * 49;
            float s0 = 0.f, s1 = 0.f, s2 = 0.f, s3 = 0.f;
            #pragma unroll
            for (int j = 0; j < 48; j += 4) {
                s0 += p[j]; s1 += p[j + 1]; s2 += p[j + 2]; s3 += p[j + 3];
            }
            g_xm[(t0 + i) * 128 + tid] =
                ((s0 + s1) + (s2 + s3) + p[48]) * (1.0f / 49.0f);
        }
        __syncthreads();                 // all reads done before refill
        if (i + 2 < 4) issue(sb[i & 1], t0 + i + 2);
    }
}

// ---------------------------------------------------------------------------
// Kernel 2 (this round's single change): projection GEMM, K-split by 8,
// packed f32x2 FMA. Tile: 32 rows x 128 cols, BK=16, 256 threads;
// thread = 2 rows x 8 cols -> 4 LDS per 8 FFMA2 (half the LDS pressure of
// the 16-row variant). grid 1024 (128 tiles x 8 K-eighths, ~7 blocks/SM).
// ---------------------------------------------------------------------------
__global__ void __launch_bounds__(256) k_proj(const float* __restrict__ pw) {
    __shared__ __align__(16) float As[16][32];
    __shared__ __align__(16) float Bs[16][128];

    int tid = threadIdx.x;
    int tx  = tid & 15;                 // col group: cols tx*8 .. tx*8+7
    int ty  = tid >> 4;                 // row group: rows ty*2, ty*2+1
    int bx  = blockIdx.x;
    int z   = bx & 7;                   // K eighth
    int m0  = (bx >> 3) * 32;           // row tile start (512 % 32 == 0)
    int b   = m0 >> 9;
    int t0  = m0 & 511;
    const float* Abase = g_xm + (size_t)b * 524288 + t0;
    const float4* pw4 = (const float4*)pw;

    int akk = tid >> 5;                 // 0..7
    int amm = tid & 31;                 // 0..31

    unsigned long long acc[2][4];
    #pragma unroll
    for (int r = 0; r < 2; r++)
        #pragma unroll
        for (int c = 0; c < 4; c++) acc[r][c] = 0ull;

    int kbeg = z * 128, kend = kbeg + 128;
    for (int k0 = kbeg; k0 < kend; k0 += 16) {
        As[akk][amm]     = Abase[(size_t)(k0 + akk)     * 512 + amm];
        As[akk + 8][amm] = Abase[(size_t)(k0 + akk + 8) * 512 + amm];
        {
            int i0 = tid, i1 = tid + 256;
            ((float4*)Bs)[i0] = pw4[(size_t)(k0 + (i0 >> 5)) * 32 + (i0 & 31)];
            ((float4*)Bs)[i1] = pw4[(size_t)(k0 + (i1 >> 5)) * 32 + (i1 & 31)];
        }
        __syncthreads();

        #pragma unroll
        for (int k = 0; k < 16; k++) {
            unsigned long long a0 = bcast2(As[k][ty * 2 + 0]);
            unsigned long long a1 = bcast2(As[k][ty * 2 + 1]);
            const ulonglong2* brow = (const ulonglong2*)Bs[k];
            ulonglong2 b0 = brow[tx * 2];
            ulonglong2 b1 = brow[tx * 2 + 1];
            fma2(acc[0][0], a0, b0.x); fma2(acc[0][1], a0, b0.y);
            fma2(acc[0][2], a0, b1.x); fma2(acc[0][3], a0, b1.y);
            fma2(acc[1][0], a1, b0.x); fma2(acc[1][1], a1, b0.y);
            fma2(acc[1][2], a1, b1.x); fma2(acc[1][3], a1, b1.y);
        }
        __syncthreads();
    }

    #pragma unroll
    for (int r = 0; r < 2; r++) {
        size_t row = (size_t)(m0 + ty * 2 + r);
        float4 v0 = make_float4(lo32(acc[r][0]), hi32(acc[r][0]),
                                lo32(acc[r][1]), hi32(acc[r][1]));
        float4 v1 = make_float4(lo32(acc[r][2]), hi32(acc[r][2]),
                                lo32(acc[r][3]), hi32(acc[r][3]));
        ((float4*)g_part)[((size_t)z * 4096 + row) * 32 + tx * 2]     = v0;
        ((float4*)g_part)[((size_t)z * 4096 + row) * 32 + tx * 2 + 1] = v1;
    }
}

// ---------------------------------------------------------------------------
// Epilogue: sum 8 partials + bias, L2 normalize, write g_y.
// ---------------------------------------------------------------------------
__global__ void __launch_bounds__(256) k_norm(const float* __restrict__ pb) {
    int tid  = threadIdx.x;
    int lane = tid & 31;
    int row  = (blockIdx.x * 256 + tid) >> 5;

    const float4* part4 = (const float4*)g_part;
    float4 v = ((const float4*)pb)[lane];
    #pragma unroll
    for (int z = 0; z < 8; z++) {
        float4 p = part4[((size_t)z * 4096 + row) * 32 + lane];
        v.x += p.x; v.y += p.y; v.z += p.z; v.w += p.w;
    }

    float ss = v.x * v.x + v.y * v.y + v.z * v.z + v.w * v.w;
    #pragma unroll
    for (int o = 16; o; o >>= 1) ss += __shfl_xor_sync(0xffffffffu, ss, o);
    float inv = 1.0f / fmaxf(sqrtf(ss), 1e-12f);
    v.x *= inv; v.y *= inv; v.z *= inv; v.w *= inv;
    ((float4*)g_y)[(size_t)row * 32 + lane] = v;
}

// ---------------------------------------------------------------------------
// Kernel 4 (proven, R13): banded cosine-sim + fc + ReLU — shuffle-free smem
// tile, 512 thr, 32 t's/block. Phase 1: (tloc, wi) 7 accs. Phase 2: 4 t/warp.
// ---------------------------------------------------------------------------
#define BAND_SMEM_FLOATS (132 * 132 + 32 * 104 + 101 * 128)
#define BAND_SMEM_BYTES  (BAND_SMEM_FLOATS * 4)

__global__ void __launch_bounds__(512) k_band_fc(const float* __restrict__ fw,
                                                 const float* __restrict__ fb,
                                                 float* __restrict__ out) {
    extern __shared__ __align__(16) float dyn[];
    float* ys  = dyn;                        // 132 x 132 (row stride 33 float4)
    float* bd  = dyn + 132 * 132;            // 32 x 104
    float* fws = bd + 32 * 104;              // 101 x 128

    int tid = threadIdx.x;
    int r0  = blockIdx.x * 32;               // first global row of this block
    int lo  = r0 & ~511;                     // batch start
    int hi  = lo + 512;

    const float4* y4   = (const float4*)g_y;
    float4*       ys4  = (float4*)ys;
    const float4* fw4  = (const float4*)fw;
    float4*       fws4 = (float4*)fws;

    // Stage y rows [r0-50, r0+82) with zero fill outside the batch.
    for (int idx = tid; idx < 132 * 32; idx += 512) {
        int rr = idx >> 5, c = idx & 31;
        int gr = r0 - 50 + rr;
        float4 v = make_float4(0.f, 0.f, 0.f, 0.f);
        if (gr >= lo && gr < hi) v = y4[(size_t)gr * 32 + c];
        ys4[rr * 33 + c] = v;
    }
    // Stage fc_w.
    for (int idx = tid; idx < 101 * 32; idx += 512) fws4[idx] = fw4[idx];
    __syncthreads();

    // ---- Phase 1: band dots ----
    {
        int tloc = tid >> 4;                 // 0..31
        int wi   = tid & 15;                 // 0..15
        float acc[7];
        #pragma unroll
        for (int j = 0; j < 7; j++) acc[j] = 0.f;

        const float4* qrow  = ys4 + (50 + tloc) * 33;
        const float4* krow0 = ys4 + tloc * 33;

        #pragma unroll 4
        for (int i = 0; i < 32; i++) {
            float4 q = qrow[i];
            #pragma unroll
            for (int j = 0; j < 7; j++) {
                int w = wi + 16 * j;
                if (w < 101) {
                    float4 k = krow0[w * 33 + i];
                    acc[j] += q.x * k.x + q.y * k.y + q.z * k.z + q.w * k.w;
                }
            }
        }
        #pragma unroll
        for (int j = 0; j < 7; j++) {
            int w = wi + 16 * j;
            if (w < 101) bd[tloc * 104 + w] = acc[j];
        }
    }
    __syncthreads();

    // ---- Phase 2: out[t] = relu(band[t] @ fc_w + fb), 4 t's per warp ----
    if (tid < 256) {
        int g    = tid >> 5;                 // warp 0..7 -> t = 4g..4g+3
        int lane = tid & 31;                 // output float4 index
        float4 a0 = make_float4(0.f, 0.f, 0.f, 0.f);
        float4 a1 = a0, a2 = a0, a3 = a0;
        const float* b0p = bd + (4 * g + 0) * 104;
        const float* b1p = bd + (4 * g + 1) * 104;
        const float* b2p = bd + (4 * g + 2) * 104;
        const float* b3p = bd + (4 * g + 3) * 104;

        for (int w = 0; w < 101; w++) {
            float4 f = fws4[w * 32 + lane];
            float s0 = b0p[w], s1 = b1p[w], s2 = b2p[w], s3 = b3p[w];
            a0.x += s0 * f.x; a0.y += s0 * f.y; a0.z += s0 * f.z; a0.w += s0 * f.w;
            a1.x += s1 * f.x; a1.y += s1 * f.y; a1.z += s1 * f.z; a1.w += s1 * f.w;
            a2.x += s2 * f.x; a2.y += s2 * f.y; a2.z += s2 * f.z; a2.w += s2 * f.w;
            a3.x += s3 * f.x; a3.y += s3 * f.y; a3.z += s3 * f.z; a3.w += s3 * f.w;
        }

        float4 bias = ((const float4*)fb)[lane];
        float4* out4 = (float4*)out;
        float4 r;
        r.x = fmaxf(a0.x + bias.x, 0.f); r.y = fmaxf(a0.y + bias.y, 0.f);
        r.z = fmaxf(a0.z + bias.z, 0.f); r.w = fmaxf(a0.w + bias.w, 0.f);
        out4[(size_t)(r0 + 4 * g + 0) * 32 + lane] = r;
        r.x = fmaxf(a1.x + bias.x, 0.f); r.y = fmaxf(a1.y + bias.y, 0.f);
        r.z = fmaxf(a1.z + bias.z, 0.f); r.w = fmaxf(a1.w + bias.w, 0.f);
        out4[(size_t)(r0 + 4 * g + 1) * 32 + lane] = r;
        r.x = fmaxf(a2.x + bias.x, 0.f); r.y = fmaxf(a2.y + bias.y, 0.f);
        r.z = fmaxf(a2.z + bias.z, 0.f); r.w = fmaxf(a2.w + bias.w, 0.f);
        out4[(size_t)(r0 + 4 * g + 2) * 32 + lane] = r;
        r.x = fmaxf(a3.x + bias.x, 0.f); r.y = fmaxf(a3.y + bias.y, 0.f);
        r.z = fmaxf(a3.z + bias.z, 0.f); r.w = fmaxf(a3.w + bias.w, 0.f);
        out4[(size_t)(r0 + 4 * g + 3) * 32 + lane] = r;
    }
}

// ---------------------------------------------------------------------------
extern "C" void kernel_launch(void* const* d_in, const int* in_sizes, int n_in,
                              void* d_out, int out_size) {
    const float* in = (const float*)d_in[0];   // [8,1024,512,7,7]
    const float* pw = (const float*)d_in[1];   // [1024,128]
    const float* pb = (const float*)d_in[2];   // [128]
    const float* fw = (const float*)d_in[3];   // [101,128]
    const float* fb = (const float*)d_in[4];   // [128]
    float* out = (float*)d_out;                // [8,512,128]

    cudaFuncSetAttribute(k_band_fc, cudaFuncAttributeMaxDynamicSharedMemorySize,
                         BAND_SMEM_BYTES);

    k_mean<<<8192, 256>>>(in);                 // 4 tiles/block, 2-stage ring
    k_proj<<<1024, 256>>>(pw);                 // 128 tiles x 8 K-eighths
    k_norm<<<512, 256>>>(pb);                  // partial sum + bias + L2 norm
    k_band_fc<<<128, 512, BAND_SMEM_BYTES>>>(fw, fb, out);  // 32 t's, 512 thr
}

// round 16
// speedup vs baseline: 1.0485x; 1.0485x over previous
#include <cuda_runtime.h>
#include <cstdint>

// Dims: B=8, C=1024, T=512, HW=49, D=128, window=101, out_dim=128.

__device__ float g_xm  [8u * 1024u * 512u];  // [B, C, T] spatial means (16.8 MB)
__device__ float g_part[8u * 4096u * 128u];  // [ksplit][b*T+t][d] GEMM partials
__device__ float g_y   [4096u * 128u];       // [B*T, 128] normalized projections

#define CP_ASYNC16(dst_u32, src_ptr) \
    asm volatile("cp.async.cg.shared.global [%0], [%1], 16;\n" \
                 :: "r"(dst_u32), "l"(src_ptr))
#define CP_COMMIT() asm volatile("cp.async.commit_group;\n" ::: "memory")
#define CP_WAIT1()  asm volatile("cp.async.wait_group 1;\n" ::: "memory")
#define CP_WAIT0()  asm volatile("cp.async.wait_group 0;\n" ::: "memory")

// Packed fp32x2 FMA (sm_100+): d = a*b + d per 32-bit half. FFMA2 in SASS.
__device__ __forceinline__ void fma2(unsigned long long& d,
                                     unsigned long long a,
                                     unsigned long long b) {
    asm("fma.rn.f32x2 %0, %1, %2, %0;" : "+l"(d) : "l"(a), "l"(b));
}
__device__ __forceinline__ unsigned long long bcast2(float x) {
    unsigned long long r;
    unsigned int u = __float_as_uint(x);
    asm("mov.b64 %0, {%1, %1};" : "=l"(r) : "r"(u));
    return r;
}
__device__ __forceinline__ float lo32(unsigned long long v) {
    return __uint_as_float((unsigned int)(v & 0xffffffffull));
}
__device__ __forceinline__ float hi32(unsigned long long v) {
    return __uint_as_float((unsigned int)(v >> 32));
}

// ---------------------------------------------------------------------------
// Kernel 1 (proven, R13): spatial mean over 49 — persistent block, 4 tiles,
// 2-stage static double-buffered cp.async. Tile = 128 rows = 25088 floats.
// Stride-49 smem reads conflict-free (gcd(49,32)=1).
// ---------------------------------------------------------------------------
__global__ void __launch_bounds__(256) k_mean(const float* __restrict__ in) {
    __shared__ __align__(16) float s[2][128 * 49];   // 2 x 25088 B
    int tid = threadIdx.x;
    unsigned int sb[2];
    sb[0] = (unsigned int)__cvta_generic_to_shared(s[0]);
    sb[1] = (unsigned int)__cvta_generic_to_shared(s[1]);
    size_t t0 = (size_t)blockIdx.x * 4;

    auto issue = [&](unsigned int base, size_t tile) {
        const float4* src = (const float4*)in + tile * 1568;
        #pragma unroll
        for (int i = 0; i < 6; i++) {
            int j = tid + i * 256;
            CP_ASYNC16(base + j * 16, src + j);
        }
        int j = tid + 1536;
        if (j < 1568) CP_ASYNC16(base + j * 16, src + j);
        CP_COMMIT();
    };

    issue(sb[0], t0);
    issue(sb[1], t0 + 1);

    #pragma unroll
    for (int i = 0; i < 4; i++) {
        if (i < 3) { CP_WAIT1(); } else { CP_WAIT0(); }
        __syncthreads();
        if (tid < 128) {
            const float* p = s[i & 1] + tid * 49;
            float s0 = 0.f, s1 = 0.f, s2 = 0.f, s3 = 0.f;
            #pragma unroll
            for (int j = 0; j < 48; j += 4) {
                s0 += p[j]; s1 += p[j + 1]; s2 += p[j + 2]; s3 += p[j + 3];
            }
            g_xm[(t0 + i) * 128 + tid] =
                ((s0 + s1) + (s2 + s3) + p[48]) * (1.0f / 49.0f);
        }
        __syncthreads();                 // all reads done before refill
        if (i + 2 < 4) issue(sb[i & 1], t0 + i + 2);
    }
}

// ---------------------------------------------------------------------------
// Kernel 2 (proven, R13): projection GEMM, K-split by 8, packed f32x2 FMA.
// Tile: 16 rows x 128 cols, BK=16; thread = 2 rows x 4 cols. grid 2048.
// ---------------------------------------------------------------------------
__global__ void __launch_bounds__(256) k_proj(const float* __restrict__ pw) {
    __shared__ __align__(16) float As[16][16];
    __shared__ __align__(16) float Bs[16][128];

    int tid = threadIdx.x;
    int tx  = tid & 31;
    int ty  = tid >> 5;
    int bx  = blockIdx.x;
    int z   = bx & 7;                   // K eighth
    int m0  = (bx >> 3) * 16;           // row tile start
    int b   = m0 >> 9;
    int t0  = m0 & 511;
    const float* Abase = g_xm + (size_t)b * 524288 + t0;
    const float4* pw4 = (const float4*)pw;

    int akk = tid >> 4;
    int amm = tid & 15;

    unsigned long long acc00 = 0ull, acc01 = 0ull;
    unsigned long long acc10 = 0ull, acc11 = 0ull;

    int kbeg = z * 128, kend = kbeg + 128;
    for (int k0 = kbeg; k0 < kend; k0 += 16) {
        As[akk][amm] = Abase[(size_t)(k0 + akk) * 512 + amm];
        {
            int i0 = tid, i1 = tid + 256;
            ((float4*)Bs)[i0] = pw4[(size_t)(k0 + (i0 >> 5)) * 32 + (i0 & 31)];
            ((float4*)Bs)[i1] = pw4[(size_t)(k0 + (i1 >> 5)) * 32 + (i1 & 31)];
        }
        __syncthreads();

        #pragma unroll
        for (int k = 0; k < 16; k++) {
            unsigned long long a0 = bcast2(As[k][ty * 2 + 0]);
            unsigned long long a1 = bcast2(As[k][ty * 2 + 1]);
            const ulonglong2* brow = (const ulonglong2*)Bs[k];
            ulonglong2 bb = brow[tx];
            fma2(acc00, a0, bb.x);
            fma2(acc01, a0, bb.y);
            fma2(acc10, a1, bb.x);
            fma2(acc11, a1, bb.y);
        }
        __syncthreads();
    }

    float4 v0 = make_float4(lo32(acc00), hi32(acc00), lo32(acc01), hi32(acc01));
    float4 v1 = make_float4(lo32(acc10), hi32(acc10), lo32(acc11), hi32(acc11));
    size_t row0 = (size_t)(m0 + ty * 2);
    ((float4*)g_part)[((size_t)z * 4096 + row0)     * 32 + tx] = v0;
    ((float4*)g_part)[((size_t)z * 4096 + row0 + 1) * 32 + tx] = v1;
}

// ---------------------------------------------------------------------------
// Epilogue: sum 8 partials + bias, L2 normalize, write g_y.
// ---------------------------------------------------------------------------
__global__ void __launch_bounds__(256) k_norm(const float* __restrict__ pb) {
    int tid  = threadIdx.x;
    int lane = tid & 31;
    int row  = (blockIdx.x * 256 + tid) >> 5;

    const float4* part4 = (const float4*)g_part;
    float4 v = ((const float4*)pb)[lane];
    #pragma unroll
    for (int z = 0; z < 8; z++) {
        float4 p = part4[((size_t)z * 4096 + row) * 32 + lane];
        v.x += p.x; v.y += p.y; v.z += p.z; v.w += p.w;
    }

    float ss = v.x * v.x + v.y * v.y + v.z * v.z + v.w * v.w;
    #pragma unroll
    for (int o = 16; o; o >>= 1) ss += __shfl_xor_sync(0xffffffffu, ss, o);
    float inv = 1.0f / fmaxf(sqrtf(ss), 1e-12f);
    v.x *= inv; v.y *= inv; v.z *= inv; v.w *= inv;
    ((float4*)g_y)[(size_t)row * 32 + lane] = v;
}

// ---------------------------------------------------------------------------
// Kernel 4: banded cosine-sim + fc + ReLU — shuffle-free smem tile, 512 thr,
// 32 t's/block. THIS ROUND'S ONLY CHANGE vs R13: fc_w is NOT staged in smem
// (phase 2 reads it via __ldg, L2-resident) -> smem 134.7 KB -> 83 KB ->
// 2 blocks/SM instead of 1, doubling resident warps for LDS-bound phase 1.
// Phase 1: thread = (tloc = tid>>4, wi = tid&15); up to 7 dot accs.
// Phase 2: 4 t's per warp, 4-way unrolled __ldg on fc_w rows.
// ---------------------------------------------------------------------------
#define BAND_SMEM_FLOATS (132 * 132 + 32 * 104)
#define BAND_SMEM_BYTES  (BAND_SMEM_FLOATS * 4)

__global__ void __launch_bounds__(512) k_band_fc(const float* __restrict__ fw,
                                                 const float* __restrict__ fb,
                                                 float* __restrict__ out) {
    extern __shared__ __align__(16) float dyn[];
    float* ys = dyn;                         // 132 x 132 (row stride 33 float4)
    float* bd = dyn + 132 * 132;             // 32 x 104

    int tid = threadIdx.x;
    int r0  = blockIdx.x * 32;               // first global row of this block
    int lo  = r0 & ~511;                     // batch start
    int hi  = lo + 512;

    const float4* y4  = (const float4*)g_y;
    float4*       ys4 = (float4*)ys;
    const float4* fw4 = (const float4*)fw;

    // Stage y rows [r0-50, r0+82) with zero fill outside the batch.
    for (int idx = tid; idx < 132 * 32; idx += 512) {
        int rr = idx >> 5, c = idx & 31;
        int gr = r0 - 50 + rr;
        float4 v = make_float4(0.f, 0.f, 0.f, 0.f);
        if (gr >= lo && gr < hi) v = y4[(size_t)gr * 32 + c];
        ys4[rr * 33 + c] = v;
    }
    __syncthreads();

    // ---- Phase 1: band dots ----
    {
        int tloc = tid >> 4;                 // 0..31
        int wi   = tid & 15;                 // 0..15
        float acc[7];
        #pragma unroll
        for (int j = 0; j < 7; j++) acc[j] = 0.f;

        const float4* qrow  = ys4 + (50 + tloc) * 33;
        const float4* krow0 = ys4 + tloc * 33;

        #pragma unroll 4
        for (int i = 0; i < 32; i++) {
            float4 q = qrow[i];
            #pragma unroll
            for (int j = 0; j < 7; j++) {
                int w = wi + 16 * j;
                if (w < 101) {
                    float4 k = krow0[w * 33 + i];
                    acc[j] += q.x * k.x + q.y * k.y + q.z * k.z + q.w * k.w;
                }
            }
        }
        #pragma unroll
        for (int j = 0; j < 7; j++) {
            int w = wi + 16 * j;
            if (w < 101) bd[tloc * 104 + w] = acc[j];
        }
    }
    __syncthreads();

    // ---- Phase 2: out[t] = relu(band[t] @ fc_w + fb), 4 t's per warp,
    //      fc_w via __ldg (4-way unrolled for MLP) ----
    if (tid < 256) {
        int g    = tid >> 5;                 // warp 0..7 -> t = 4g..4g+3
        int lane = tid & 31;                 // output float4 index
        float4 a0 = make_float4(0.f, 0.f, 0.f, 0.f);
        float4 a1 = a0, a2 = a0, a3 = a0;
        const float* b0p = bd + (4 * g + 0) * 104;
        const float* b1p = bd + (4 * g + 1) * 104;
        const float* b2p = bd + (4 * g + 2) * 104;
        const float* b3p = bd + (4 * g + 3) * 104;

        int w = 0;
        #pragma unroll 1
        for (; w + 3 < 101; w += 4) {
            float4 f0 = __ldg(fw4 + (w + 0) * 32 + lane);
            float4 f1 = __ldg(fw4 + (w + 1) * 32 + lane);
            float4 f2 = __ldg(fw4 + (w + 2) * 32 + lane);
            float4 f3 = __ldg(fw4 + (w + 3) * 32 + lane);
            #pragma unroll
            for (int u = 0; u < 4; u++) {
                const float4& f = (u == 0) ? f0 : (u == 1) ? f1 : (u == 2) ? f2 : f3;
                float s0 = b0p[w + u], s1 = b1p[w + u];
                float s2 = b2p[w + u], s3 = b3p[w + u];
                a0.x += s0 * f.x; a0.y += s0 * f.y; a0.z += s0 * f.z; a0.w += s0 * f.w;
                a1.x += s1 * f.x; a1.y += s1 * f.y; a1.z += s1 * f.z; a1.w += s1 * f.w;
                a2.x += s2 * f.x; a2.y += s2 * f.y; a2.z += s2 * f.z; a2.w += s2 * f.w;
                a3.x += s3 * f.x; a3.y += s3 * f.y; a3.z += s3 * f.z; a3.w += s3 * f.w;
            }
        }
        {   // tail w = 100
            float4 f = __ldg(fw4 + 100 * 32 + lane);
            float s0 = b0p[100], s1 = b1p[100], s2 = b2p[100], s3 = b3p[100];
            a0.x += s0 * f.x; a0.y += s0 * f.y; a0.z += s0 * f.z; a0.w += s0 * f.w;
            a1.x += s1 * f.x; a1.y += s1 * f.y; a1.z += s1 * f.z; a1.w += s1 * f.w;
            a2.x += s2 * f.x; a2.y += s2 * f.y; a2.z += s2 * f.z; a2.w += s2 * f.w;
            a3.x += s3 * f.x; a3.y += s3 * f.y; a3.z += s3 * f.z; a3.w += s3 * f.w;
        }

        float4 bias = ((const float4*)fb)[lane];
        float4* out4 = (float4*)out;
        float4 r;
        r.x = fmaxf(a0.x + bias.x, 0.f); r.y = fmaxf(a0.y + bias.y, 0.f);
        r.z = fmaxf(a0.z + bias.z, 0.f); r.w = fmaxf(a0.w + bias.w, 0.f);
        out4[(size_t)(r0 + 4 * g + 0) * 32 + lane] = r;
        r.x = fmaxf(a1.x + bias.x, 0.f); r.y = fmaxf(a1.y + bias.y, 0.f);
        r.z = fmaxf(a1.z + bias.z, 0.f); r.w = fmaxf(a1.w + bias.w, 0.f);
        out4[(size_t)(r0 + 4 * g + 1) * 32 + lane] = r;
        r.x = fmaxf(a2.x + bias.x, 0.f); r.y = fmaxf(a2.y + bias.y, 0.f);
        r.z = fmaxf(a2.z + bias.z, 0.f); r.w = fmaxf(a2.w + bias.w, 0.f);
        out4[(size_t)(r0 + 4 * g + 2) * 32 + lane] = r;
        r.x = fmaxf(a3.x + bias.x, 0.f); r.y = fmaxf(a3.y + bias.y, 0.f);
        r.z = fmaxf(a3.z + bias.z, 0.f); r.w = fmaxf(a3.w + bias.w, 0.f);
        out4[(size_t)(r0 + 4 * g + 3) * 32 + lane] = r;
    }
}

// ---------------------------------------------------------------------------
extern "C" void kernel_launch(void* const* d_in, const int* in_sizes, int n_in,
                              void* d_out, int out_size) {
    const float* in = (const float*)d_in[0];   // [8,1024,512,7,7]
    const float* pw = (const float*)d_in[1];   // [1024,128]
    const float* pb = (const float*)d_in[2];   // [128]
    const float* fw = (const float*)d_in[3];   // [101,128]
    const float* fb = (const float*)d_in[4];   // [128]
    float* out = (float*)d_out;                // [8,512,128]

    cudaFuncSetAttribute(k_band_fc, cudaFuncAttributeMaxDynamicSharedMemorySize,
                         BAND_SMEM_BYTES);

    k_mean<<<8192, 256>>>(in);                 // 4 tiles/block, 2-stage ring
    k_proj<<<2048, 256>>>(pw);                 // 256 tiles x 8 K-eighths
    k_norm<<<512, 256>>>(pb);                  // partial sum + bias + L2 norm
    k_band_fc<<<128, 512, BAND_SMEM_BYTES>>>(fw, fb, out);  // 32 t's, 512 thr
}

// round 17
// speedup vs baseline: 1.1293x; 1.0771x over previous
#include <cuda_runtime.h>
#include <cstdint>

// Dims: B=8, C=1024, T=512, HW=49, D=128, window=101, out_dim=128.

__device__ float g_xm  [8u * 1024u * 512u];  // [B, C, T] spatial means (16.8 MB)
__device__ float g_part[8u * 4096u * 128u];  // [ksplit][b*T+t][d] GEMM partials
__device__ float g_y   [4096u * 128u];       // [B*T, 128] normalized projections

#define CP_ASYNC16(dst_u32, src_ptr) \
    asm volatile("cp.async.cg.shared.global [%0], [%1], 16;\n" \
                 :: "r"(dst_u32), "l"(src_ptr))
#define CP_COMMIT() asm volatile("cp.async.commit_group;\n" ::: "memory")
#define CP_WAIT1()  asm volatile("cp.async.wait_group 1;\n" ::: "memory")
#define CP_WAIT0()  asm volatile("cp.async.wait_group 0;\n" ::: "memory")

// Packed fp32x2 FMA (sm_100+): d = a*b + d per 32-bit half. FFMA2 in SASS.
__device__ __forceinline__ void fma2(unsigned long long& d,
                                     unsigned long long a,
                                     unsigned long long b) {
    asm("fma.rn.f32x2 %0, %1, %2, %0;" : "+l"(d) : "l"(a), "l"(b));
}
__device__ __forceinline__ unsigned long long bcast2(float x) {
    unsigned long long r;
    unsigned int u = __float_as_uint(x);
    asm("mov.b64 %0, {%1, %1};" : "=l"(r) : "r"(u));
    return r;
}
__device__ __forceinline__ float lo32(unsigned long long v) {
    return __uint_as_float((unsigned int)(v & 0xffffffffull));
}
__device__ __forceinline__ float hi32(unsigned long long v) {
    return __uint_as_float((unsigned int)(v >> 32));
}

// ---------------------------------------------------------------------------
// Kernel 1 (proven, R13): spatial mean over 49 — persistent block, 4 tiles,
// 2-stage static double-buffered cp.async. Tile = 128 rows = 25088 floats.
// Stride-49 smem reads conflict-free (gcd(49,32)=1).
// ---------------------------------------------------------------------------
__global__ void __launch_bounds__(256) k_mean(const float* __restrict__ in) {
    __shared__ __align__(16) float s[2][128 * 49];   // 2 x 25088 B
    int tid = threadIdx.x;
    unsigned int sb[2];
    sb[0] = (unsigned int)__cvta_generic_to_shared(s[0]);
    sb[1] = (unsigned int)__cvta_generic_to_shared(s[1]);
    size_t t0 = (size_t)blockIdx.x * 4;

    auto issue = [&](unsigned int base, size_t tile) {
        const float4* src = (const float4*)in + tile * 1568;
        #pragma unroll
        for (int i = 0; i < 6; i++) {
            int j = tid + i * 256;
            CP_ASYNC16(base + j * 16, src + j);
        }
        int j = tid + 1536;
        if (j < 1568) CP_ASYNC16(base + j * 16, src + j);
        CP_COMMIT();
    };

    issue(sb[0], t0);
    issue(sb[1], t0 + 1);

    #pragma unroll
    for (int i = 0; i < 4; i++) {
        if (i < 3) { CP_WAIT1(); } else { CP_WAIT0(); }
        __syncthreads();
        if (tid < 128) {
            const float* p = s[i & 1] + tid * 49;
            float s0 = 0.f, s1 = 0.f, s2 = 0.f, s3 = 0.f;
            #pragma unroll
            for (int j = 0; j < 48; j += 4) {
                s0 += p[j]; s1 += p[j + 1]; s2 += p[j + 2]; s3 += p[j + 3];
            }
            g_xm[(t0 + i) * 128 + tid] =
                ((s0 + s1) + (s2 + s3) + p[48]) * (1.0f / 49.0f);
        }
        __syncthreads();                 // all reads done before refill
        if (i + 2 < 4) issue(sb[i & 1], t0 + i + 2);
    }
}

// ---------------------------------------------------------------------------
// Kernel 2 (this round's single change): projection GEMM, K-split by 8,
// packed f32x2 FMA, REGISTER-PREFETCH double buffering — next k-tile's
// global loads are issued before the FMA phase, overlapping LDG latency
// with compute. Tile: 16 rows x 128 cols, BK=16; thread = 2r x 4c. grid 2048.
// ---------------------------------------------------------------------------
__global__ void __launch_bounds__(256) k_proj(const float* __restrict__ pw) {
    __shared__ __align__(16) float As[16][16];
    __shared__ __align__(16) float Bs[16][128];

    int tid = threadIdx.x;
    int tx  = tid & 31;
    int ty  = tid >> 5;
    int bx  = blockIdx.x;
    int z   = bx & 7;                   // K eighth
    int m0  = (bx >> 3) * 16;           // row tile start
    int b   = m0 >> 9;
    int t0  = m0 & 511;
    const float* Abase = g_xm + (size_t)b * 524288 + t0;
    const float4* pw4 = (const float4*)pw;

    int akk = tid >> 4;                 // 0..15 (k within tile)
    int amm = tid & 15;                 // 0..15 (m within tile)
    int bk0 = tid >> 5;                 // Bs row for slot 0
    int bc0 = tid & 31;                 // Bs col (float4) for both slots
    int bk1 = (tid + 256) >> 5;         // Bs row for slot 1

    unsigned long long acc00 = 0ull, acc01 = 0ull;
    unsigned long long acc10 = 0ull, acc11 = 0ull;

    int kbeg = z * 128, kend = kbeg + 128;

    // Preload first tile into registers.
    float  a_reg  = Abase[(size_t)(kbeg + akk) * 512 + amm];
    float4 b_reg0 = pw4[(size_t)(kbeg + bk0) * 32 + bc0];
    float4 b_reg1 = pw4[(size_t)(kbeg + bk1) * 32 + bc0];

    for (int k0 = kbeg; k0 < kend; k0 += 16) {
        // Store the prefetched tile.
        As[akk][amm]            = a_reg;
        ((float4*)Bs)[tid]      = b_reg0;
        ((float4*)Bs)[tid + 256] = b_reg1;
        __syncthreads();

        // Prefetch NEXT tile (overlaps with FMA phase below).
        if (k0 + 16 < kend) {
            a_reg  = Abase[(size_t)(k0 + 16 + akk) * 512 + amm];
            b_reg0 = pw4[(size_t)(k0 + 16 + bk0) * 32 + bc0];
            b_reg1 = pw4[(size_t)(k0 + 16 + bk1) * 32 + bc0];
        }

        #pragma unroll
        for (int k = 0; k < 16; k++) {
            unsigned long long a0 = bcast2(As[k][ty * 2 + 0]);
            unsigned long long a1 = bcast2(As[k][ty * 2 + 1]);
            const ulonglong2* brow = (const ulonglong2*)Bs[k];
            ulonglong2 bb = brow[tx];
            fma2(acc00, a0, bb.x);
            fma2(acc01, a0, bb.y);
            fma2(acc10, a1, bb.x);
            fma2(acc11, a1, bb.y);
        }
        __syncthreads();
    }

    float4 v0 = make_float4(lo32(acc00), hi32(acc00), lo32(acc01), hi32(acc01));
    float4 v1 = make_float4(lo32(acc10), hi32(acc10), lo32(acc11), hi32(acc11));
    size_t row0 = (size_t)(m0 + ty * 2);
    ((float4*)g_part)[((size_t)z * 4096 + row0)     * 32 + tx] = v0;
    ((float4*)g_part)[((size_t)z * 4096 + row0 + 1) * 32 + tx] = v1;
}

// ---------------------------------------------------------------------------
// Epilogue: sum 8 partials + bias, L2 normalize, write g_y.
// ---------------------------------------------------------------------------
__global__ void __launch_bounds__(256) k_norm(const float* __restrict__ pb) {
    int tid  = threadIdx.x;
    int lane = tid & 31;
    int row  = (blockIdx.x * 256 + tid) >> 5;

    const float4* part4 = (const float4*)g_part;
    float4 v = ((const float4*)pb)[lane];
    #pragma unroll
    for (int z = 0; z < 8; z++) {
        float4 p = part4[((size_t)z * 4096 + row) * 32 + lane];
        v.x += p.x; v.y += p.y; v.z += p.z; v.w += p.w;
    }

    float ss = v.x * v.x + v.y * v.y + v.z * v.z + v.w * v.w;
    #pragma unroll
    for (int o = 16; o; o >>= 1) ss += __shfl_xor_sync(0xffffffffu, ss, o);
    float inv = 1.0f / fmaxf(sqrtf(ss), 1e-12f);
    v.x *= inv; v.y *= inv; v.z *= inv; v.w *= inv;
    ((float4*)g_y)[(size_t)row * 32 + lane] = v;
}

// ---------------------------------------------------------------------------
// Kernel 4 (proven, R13): banded cosine-sim + fc + ReLU — shuffle-free smem
// tile, 512 thr, 32 t's/block, fc_w staged. Phase 1: (tloc, wi) 7 accs.
// Phase 2: 4 t's per warp.
// ---------------------------------------------------------------------------
#define BAND_SMEM_FLOATS (132 * 132 + 32 * 104 + 101 * 128)
#define BAND_SMEM_BYTES  (BAND_SMEM_FLOATS * 4)

__global__ void __launch_bounds__(512) k_band_fc(const float* __restrict__ fw,
                                                 const float* __restrict__ fb,
                                                 float* __restrict__ out) {
    extern __shared__ __align__(16) float dyn[];
    float* ys  = dyn;                        // 132 x 132 (row stride 33 float4)
    float* bd  = dyn + 132 * 132;            // 32 x 104
    float* fws = bd + 32 * 104;              // 101 x 128

    int tid = threadIdx.x;
    int r0  = blockIdx.x * 32;               // first global row of this block
    int lo  = r0 & ~511;                     // batch start
    int hi  = lo + 512;

    const float4* y4   = (const float4*)g_y;
    float4*       ys4  = (float4*)ys;
    const float4* fw4  = (const float4*)fw;
    float4*       fws4 = (float4*)fws;

    // Stage y rows [r0-50, r0+82) with zero fill outside the batch.
    for (int idx = tid; idx < 132 * 32; idx += 512) {
        int rr = idx >> 5, c = idx & 31;
        int gr = r0 - 50 + rr;
        float4 v = make_float4(0.f, 0.f, 0.f, 0.f);
        if (gr >= lo && gr < hi) v = y4[(size_t)gr * 32 + c];
        ys4[rr * 33 + c] = v;
    }
    // Stage fc_w.
    for (int idx = tid; idx < 101 * 32; idx += 512) fws4[idx] = fw4[idx];
    __syncthreads();

    // ---- Phase 1: band dots ----
    {
        int tloc = tid >> 4;                 // 0..31
        int wi   = tid & 15;                 // 0..15
        float acc[7];
        #pragma unroll
        for (int j = 0; j < 7; j++) acc[j] = 0.f;

        const float4* qrow  = ys4 + (50 + tloc) * 33;
        const float4* krow0 = ys4 + tloc * 33;

        #pragma unroll 4
        for (int i = 0; i < 32; i++) {
            float4 q = qrow[i];
            #pragma unroll
            for (int j = 0; j < 7; j++) {
                int w = wi + 16 * j;
                if (w < 101) {
                    float4 k = krow0[w * 33 + i];
                    acc[j] += q.x * k.x + q.y * k.y + q.z * k.z + q.w * k.w;
                }
            }
        }
        #pragma unroll
        for (int j = 0; j < 7; j++) {
            int w = wi + 16 * j;
            if (w < 101) bd[tloc * 104 + w] = acc[j];
        }
    }
    __syncthreads();

    // ---- Phase 2: out[t] = relu(band[t] @ fc_w + fb), 4 t's per warp ----
    if (tid < 256) {
        int g    = tid >> 5;                 // warp 0..7 -> t = 4g..4g+3
        int lane = tid & 31;                 // output float4 index
        float4 a0 = make_float4(0.f, 0.f, 0.f, 0.f);
        float4 a1 = a0, a2 = a0, a3 = a0;
        const float* b0p = bd + (4 * g + 0) * 104;
        const float* b1p = bd + (4 * g + 1) * 104;
        const float* b2p = bd + (4 * g + 2) * 104;
        const float* b3p = bd + (4 * g + 3) * 104;

        for (int w = 0; w < 101; w++) {
            float4 f = fws4[w * 32 + lane];
            float s0 = b0p[w], s1 = b1p[w], s2 = b2p[w], s3 = b3p[w];
            a0.x += s0 * f.x; a0.y += s0 * f.y; a0.z += s0 * f.z; a0.w += s0 * f.w;
            a1.x += s1 * f.x; a1.y += s1 * f.y; a1.z += s1 * f.z; a1.w += s1 * f.w;
            a2.x += s2 * f.x; a2.y += s2 * f.y; a2.z += s2 * f.z; a2.w += s2 * f.w;
            a3.x += s3 * f.x; a3.y += s3 * f.y; a3.z += s3 * f.z; a3.w += s3 * f.w;
        }

        float4 bias = ((const float4*)fb)[lane];
        float4* out4 = (float4*)out;
        float4 r;
        r.x = fmaxf(a0.x + bias.x, 0.f); r.y = fmaxf(a0.y + bias.y, 0.f);
        r.z = fmaxf(a0.z + bias.z, 0.f); r.w = fmaxf(a0.w + bias.w, 0.f);
        out4[(size_t)(r0 + 4 * g + 0) * 32 + lane] = r;
        r.x = fmaxf(a1.x + bias.x, 0.f); r.y = fmaxf(a1.y + bias.y, 0.f);
        r.z = fmaxf(a1.z + bias.z, 0.f); r.w = fmaxf(a1.w + bias.w, 0.f);
        out4[(size_t)(r0 + 4 * g + 1) * 32 + lane] = r;
        r.x = fmaxf(a2.x + bias.x, 0.f); r.y = fmaxf(a2.y + bias.y, 0.f);
        r.z = fmaxf(a2.z + bias.z, 0.f); r.w = fmaxf(a2.w + bias.w, 0.f);
        out4[(size_t)(r0 + 4 * g + 2) * 32 + lane] = r;
        r.x = fmaxf(a3.x + bias.x, 0.f); r.y = fmaxf(a3.y + bias.y, 0.f);
        r.z = fmaxf(a3.z + bias.z, 0.f); r.w = fmaxf(a3.w + bias.w, 0.f);
        out4[(size_t)(r0 + 4 * g + 3) * 32 + lane] = r;
    }
}

// ---------------------------------------------------------------------------
extern "C" void kernel_launch(void* const* d_in, const int* in_sizes, int n_in,
                              void* d_out, int out_size) {
    const float* in = (const float*)d_in[0];   // [8,1024,512,7,7]
    const float* pw = (const float*)d_in[1];   // [1024,128]
    const float* pb = (const float*)d_in[2];   // [128]
    const float* fw = (const float*)d_in[3];   // [101,128]
    const float* fb = (const float*)d_in[4];   // [128]
    float* out = (float*)d_out;                // [8,512,128]

    cudaFuncSetAttribute(k_band_fc, cudaFuncAttributeMaxDynamicSharedMemorySize,
                         BAND_SMEM_BYTES);

    k_mean<<<8192, 256>>>(in);                 // 4 tiles/block, 2-stage ring
    k_proj<<<2048, 256>>>(pw);                 // 256 tiles x 8 K-eighths
    k_norm<<<512, 256>>>(pb);                  // partial sum + bias + L2 norm
    k_band_fc<<<128, 512, BAND_SMEM_BYTES>>>(fw, fb, out);  // 32 t's, 512 thr
}